// round 10
// baseline (speedup 1.0000x reference)
#include <cuda_runtime.h>

// HMM forward CgpHmmCell (nCodons=2): 24 states + 2 helper lanes, batch=2048, T=2000.
// One warp per sequence, one lane per state; <=2 sources/lane (2 shfl + 1 LDS).
// R10: WPB=2 (balance), E folded into coefs off-chain, E regs double-buffered
// one block ahead, delayed renormalization (butterfly off critical path).

#define T_LEN 2000
#define BATCH 2048
#define WPB   2
#define BLOCK (WPB * 32)

__device__ int2   g_src[32];
__device__ float2 g_cp[32];
__device__ float2 g_cr[32];
__device__ float  g_dsc[32];
__device__ float  g_invd[32];
__device__ float  g_pi[24];
__device__ float  g_Etab[64 * 32];

// ---------------------------------------------------------------------------
// Setup (identical tables to R9)
// ---------------------------------------------------------------------------
__global__ void setup_kernel(const float* __restrict__ w,
                             const float* __restrict__ ew,
                             const float* __restrict__ ik) {
    int tid = threadIdx.x;
    if (tid == 0) {
        float w12 = w[12];
        float d1 = 1.0f - w12 * w12;
        float d2 = 1.0f - w12 * w12 * w12;
        float a00, a01, a34, a314, a37, a310, a67, a617, a610,
              a920, a910, a164, a1614, a197, a1917, a2210, a2220;
        {
            float v0 = 1.0f - w[0], v1 = w[0];
            float m = fmaxf(v0, v1);
            float e0 = expf(v0 - m), e1 = expf(v1 - m);
            float s = e0 + e1;
            a00 = e0 / s; a01 = e1 / s;
        }
        {
            float v0 = w[1], v1 = w[3], v2 = d1, v3 = d2;
            float m = fmaxf(fmaxf(v0, v1), fmaxf(v2, v3));
            float e0 = expf(v0 - m), e1 = expf(v1 - m), e2 = expf(v2 - m), e3 = expf(v3 - m);
            float s = e0 + e1 + e2 + e3;
            a34 = e0 / s; a314 = e1 / s; a37 = e2 / s; a310 = e3 / s;
        }
        {
            float v0 = w[2], v1 = w[4], v2 = d1;
            float m = fmaxf(fmaxf(v0, v1), v2);
            float e0 = expf(v0 - m), e1 = expf(v1 - m), e2 = expf(v2 - m);
            float s = e0 + e1 + e2;
            a67 = e0 / s; a617 = e1 / s; a610 = e2 / s;
        }
        {
            float v0 = w[5], v1 = 1.0f - w[5];
            float m = fmaxf(v0, v1);
            float e0 = expf(v0 - m), e1 = expf(v1 - m);
            float s = e0 + e1;
            a920 = e0 / s; a910 = e1 / s;
        }
        {
            float v0 = w[6], v1 = 1.0f - w[9];
            float m = fmaxf(v0, v1);
            float e0 = expf(v0 - m), e1 = expf(v1 - m);
            float s = e0 + e1;
            a164 = e0 / s; a1614 = e1 / s;
        }
        {
            float v0 = w[7], v1 = 1.0f - w[10];
            float m = fmaxf(v0, v1);
            float e0 = expf(v0 - m), e1 = expf(v1 - m);
            float s = e0 + e1;
            a197 = e0 / s; a1917 = e1 / s;
        }
        {
            float v0 = w[8], v1 = 1.0f - w[11];
            float m = fmaxf(v0, v1);
            float e0 = expf(v0 - m), e1 = expf(v1 - m);
            float s = e0 + e1;
            a2210 = e0 / s; a2220 = e1 / s;
        }
        const float S6 = 1.0f / 6.0f, S36 = 1.0f / 36.0f, S216 = 1.0f / 216.0f;

        for (int l = 0; l < 32; l++) {
            g_src[l]  = make_int2(l, l);
            g_cp[l]   = make_float2(0.f, 0.f);
            g_cr[l]   = make_float2(0.f, 0.f);
            g_dsc[l]  = 1.0f;
            g_invd[l] = 1.0f;
        }
        g_src[0]  = make_int2(0, 0);   g_cp[0]  = make_float2(a00, 0);          g_cr[0]  = g_cp[0];
        g_src[1]  = make_int2(0, 1);   g_cp[1]  = make_float2(a01, 0);          g_cr[1]  = g_cp[1];
        g_src[2]  = make_int2(1, 2);   g_cp[2]  = make_float2(1, 0);            g_cr[2]  = g_cp[2];
        g_src[3]  = make_int2(2, 3);   g_cp[3]  = make_float2(1, 0);            g_cr[3]  = g_cp[3];
        g_src[4]  = make_int2(3, 16);  g_cp[4]  = make_float2(a34, a164);       g_cr[4]  = g_cp[4];
        g_src[5]  = make_int2(4, 5);   g_cp[5]  = make_float2(1, 0);            g_cr[5]  = g_cp[5];
        g_src[6]  = make_int2(5, 6);   g_cp[6]  = make_float2(1, 0);            g_cr[6]  = g_cp[6];
        g_src[7]  = make_int2(3, 6);   g_cp[7]  = make_float2(a37, a67);        g_cr[7]  = g_cp[7];
        g_src[8]  = make_int2(7, 25);  g_cp[8]  = make_float2(1, 1);            g_cr[8]  = g_cp[8];
        g_src[9]  = make_int2(8, 9);   g_cp[9]  = make_float2(1, 0);            g_cr[9]  = g_cp[9];
        g_src[10] = make_int2(3, 6);   g_cp[10] = make_float2(a310, a610);      g_cr[10] = g_cp[10];
        g_src[11] = make_int2(10, 24); g_cp[11] = make_float2(1, 1);            g_cr[11] = g_cp[11];
        g_src[12] = make_int2(11, 12); g_cp[12] = make_float2(1, 0);            g_cr[12] = g_cp[12];
        g_src[13] = make_int2(12, 13); g_cp[13] = make_float2(1, 0.5f);         g_cr[13] = g_cp[13];
        g_src[14] = make_int2(3, 16);  g_cp[14] = make_float2(a314, a1614);     g_cr[14] = g_cp[14];
        g_src[15] = make_int2(14, 15); g_cp[15] = make_float2(1, 0);            g_cr[15] = g_cp[15];
        g_src[16] = make_int2(15, 16); g_cp[16] = make_float2(1, 0);            g_cr[16] = g_cp[16];
        g_src[17] = make_int2(6, 19);  g_cp[17] = make_float2(a617 * S6, a1917 * S216);
                                       g_cr[17] = make_float2(a617, a1917);
        g_src[18] = make_int2(17, 18); g_cp[18] = make_float2(1, 0);            g_cr[18] = g_cp[18];
        g_src[19] = make_int2(18, 19); g_cp[19] = make_float2(1, 0);            g_cr[19] = g_cp[19];
        g_src[20] = make_int2(9, 22);  g_cp[20] = make_float2(a920 * S6, a2220 * S216);
                                       g_cr[20] = make_float2(a920, a2220);
        g_src[21] = make_int2(20, 21); g_cp[21] = make_float2(1, 0);            g_cr[21] = g_cp[21];
        g_src[22] = make_int2(21, 22); g_cp[22] = make_float2(1, 0);            g_cr[22] = g_cp[22];
        g_src[23] = make_int2(13, 23); g_cp[23] = make_float2(0.5f * S6, S6);
                                       g_cr[23] = make_float2(0.5f, 1.0f);
        g_src[24] = make_int2(9, 22);  g_cp[24] = make_float2(a910, a2210 * S36);
                                       g_cr[24] = make_float2(a910, a2210);
        g_src[25] = make_int2(19, 25); g_cp[25] = make_float2(a197 * S36, 0);
                                       g_cr[25] = make_float2(a197, 0);
        g_dsc[18] = 6.0f;  g_invd[18] = S6;
        g_dsc[19] = 36.0f; g_invd[19] = S36;
        g_dsc[21] = 6.0f;  g_invd[21] = S6;
        g_dsc[22] = 36.0f; g_invd[22] = S36;
        {
            float m = -1e30f;
            for (int i = 0; i < 24; i++) m = fmaxf(m, ik[i]);
            float e[24]; float s = 0.0f;
            for (int i = 0; i < 24; i++) { e[i] = expf(ik[i] - m); s += e[i]; }
            for (int i = 0; i < 24; i++) g_pi[i] = e[i] / s;
        }
    }
    __syncthreads();

    for (int idx = tid; idx < 64 * 32; idx += blockDim.x) {
        int ctx = idx >> 5;
        int l   = idx & 31;
        int st  = (l < 17) ? l : (l == 24) ? 10 : (l == 25) ? 7 : -1;
        float val;
        if (st >= 0) {
            int pq = ctx >> 2;
            int c  = ctx & 3;
            const float* p = ew + st * 64 + pq * 4;
            float v0 = p[0], v1 = p[1], v2 = p[2], v3 = p[3];
            float m = fmaxf(fmaxf(v0, v1), fmaxf(v2, v3));
            float e0 = expf(v0 - m), e1 = expf(v1 - m),
                  e2 = expf(v2 - m), e3 = expf(v3 - m);
            float ss = e0 + e1 + e2 + e3;
            float ec = (c == 0) ? e0 : (c == 1) ? e1 : (c == 2) ? e2 : e3;
            val = ec / ss;
        } else if (l < 24) {
            val = 1.0f;
        } else {
            val = 0.0f;
        }
        g_Etab[idx] = val;
    }
}

// ---------------------------------------------------------------------------
// Forward kernel
// ---------------------------------------------------------------------------
__global__ __launch_bounds__(BLOCK)
void forward_kernel(const int* __restrict__ seq, float* __restrict__ out) {
    __shared__ __align__(16) float Tb[64 * 32];
    {
        const float4* src = reinterpret_cast<const float4*>(g_Etab);
        float4* dst = reinterpret_cast<float4*>(Tb);
        for (int i = threadIdx.x; i < 64 * 32 / 4; i += BLOCK) dst[i] = src[i];
    }
    __syncthreads();

    const unsigned FULL = 0xffffffffu;
    const int lane = threadIdx.x & 31;
    const int wid  = blockIdx.x * WPB + (threadIdx.x >> 5);

    const int2   si = g_src[lane];
    const float2 cp = g_cp[lane];
    const float  invd = g_invd[lane];
    const float* TbL = Tb + lane;

    const int4* q4 = reinterpret_cast<const int4*>(seq + wid * T_LEN);

    float beta = (lane < 24) ? g_pi[lane] : 0.0f;

    // t=1: raw-coef transition step, then beta scale.
    {
        const float2 cr = g_cr[lane];
        const float  dsc = g_dsc[lane];
        float x0 = __shfl_sync(FULL, beta, si.x);
        float x1 = __shfl_sync(FULL, beta, si.y);
        beta = dsc * fmaf(cr.y, x1, cr.x * x0);
    }

    float ll = -3.58351893845611f;   // 2 * ln(1/6)

    // E-folded step: g0/g1 computed off-chain while shuffles are in flight.
#define STEP(EV) do { \
        float x0 = __shfl_sync(FULL, beta, si.x); \
        float x1 = __shfl_sync(FULL, beta, si.y); \
        float g0 = (EV) * cp.x; \
        float g1 = (EV) * cp.y; \
        beta = fmaf(g1, x1, g0 * x0); \
    } while (0)

    // t=2, t=3
    int4 v = q4[0];
    int ctx;
    {
        int c2 = ((v.x << 4) | (v.y << 2) | v.z) & 63;
        int c3 = ((c2 << 2) | v.w) & 63;
        float e2 = TbL[c2 << 5];
        float e3 = TbL[c3 << 5];
        STEP(e2);
        STEP(e3);
        ctx = c3;
    }

    // Preload E rows for block 1; seq prefetch distance 2.
    int4 u1 = q4[2];                 // seq for block 2
    float e0, e1, e2, e3;
    {
        int4 u0 = q4[1];
        int c0 = ((ctx << 2) | u0.x) & 63;
        int c1 = ((c0  << 2) | u0.y) & 63;
        int c2c = ((c1 << 2) | u0.z) & 63;
        int c3c = ((c2c << 2) | u0.w) & 63;
        ctx = c3c;
        e0 = TbL[c0 << 5];
        e1 = TbL[c1 << 5];
        e2 = TbL[c2c << 5];
        e3 = TbL[c3c << 5];
    }

    float pending_inv = 1.0f;        // delayed renormalization factor

    for (int j = 1; j < 500; ++j) {
        int jn = (j < 498) ? j + 2 : 499;
        int4 up = q4[jn];            // seq for block j+2

        // Compute next block's contexts + issue its E loads (off-chain).
        int n0 = ((ctx << 2) | u1.x) & 63;
        int n1 = ((n0  << 2) | u1.y) & 63;
        int n2 = ((n1  << 2) | u1.z) & 63;
        int n3 = ((n2  << 2) | u1.w) & 63;
        ctx = n3;
        float f0 = TbL[n0 << 5];
        float f1 = TbL[n1 << 5];
        float f2 = TbL[n2 << 5];
        float f3 = TbL[n3 << 5];

        // Run block j with preloaded E.
        STEP(e0);
        STEP(e1);
        STEP(e2);
        STEP(e3);

        if ((j & 3) == 3) {          // every 16 steps
            beta *= pending_inv;     // apply previous checkpoint's factor (on chain)
            float t = beta;          // butterfly + log + rcp: off critical path
            t += __shfl_xor_sync(FULL, t, 16);
            t += __shfl_xor_sync(FULL, t, 8);
            t += __shfl_xor_sync(FULL, t, 4);
            t += __shfl_xor_sync(FULL, t, 2);
            t += __shfl_xor_sync(FULL, t, 1);
            ll += __logf(t);
            pending_inv = __fdividef(1.0f, t);
        }

        e0 = f0; e1 = f1; e2 = f2; e3 = f3;
        u1 = up;
    }
#undef STEP

    // Final: apply pending factor, beta -> alpha mass correction.
    {
        beta *= pending_inv;
        float t = beta * invd;
        t += __shfl_xor_sync(FULL, t, 16);
        t += __shfl_xor_sync(FULL, t, 8);
        t += __shfl_xor_sync(FULL, t, 4);
        t += __shfl_xor_sync(FULL, t, 2);
        t += __shfl_xor_sync(FULL, t, 1);
        ll += __logf(t);
    }

    if (lane == 0) out[wid] = ll;
}

// ---------------------------------------------------------------------------
// Launch
// ---------------------------------------------------------------------------
extern "C" void kernel_launch(void* const* d_in, const int* in_sizes, int n_in,
                              void* d_out, int out_size) {
    const float* transition_kernel = (const float*)d_in[0];
    const float* emission_kernel   = (const float*)d_in[1];
    const float* init_kernel       = (const float*)d_in[2];
    const int*   seq               = (const int*)d_in[3];
    float* out = (float*)d_out;

    setup_kernel<<<1, 256>>>(transition_kernel, emission_kernel, init_kernel);
    forward_kernel<<<BATCH / WPB, BLOCK>>>(seq, out);
}

// round 11
// speedup vs baseline: 1.0404x; 1.0404x over previous
#include <cuda_runtime.h>

// HMM forward CgpHmmCell (nCodons=2): 24 states + 2 helper lanes, batch=2048, T=2000.
// One warp per sequence, one lane per state; <=2 sources/lane.
// R11: E*coef fully folded into a per-[ctx][lane] float2 table (no extra muls):
// step = 2 shfl + 1 LDS.64 + mul + fma. Renorm every 32 steps, delayed apply.

#define T_LEN 2000
#define BATCH 2048
#define WPB   2
#define BLOCK (WPB * 32)

__device__ int2   g_src[32];
__device__ float2 g_cp[32];       // beta-rescaled coefficients (pre-E)
__device__ float2 g_cr[32];       // raw coefficients (t=1 step)
__device__ float  g_dsc[32];
__device__ float  g_invd[32];
__device__ float  g_pi[24];
__device__ float2 g_Gtab[64 * 32]; // [ctx][lane] = (E*cp.x, E*cp.y)

// ---------------------------------------------------------------------------
// Setup
// ---------------------------------------------------------------------------
__global__ void setup_kernel(const float* __restrict__ w,
                             const float* __restrict__ ew,
                             const float* __restrict__ ik) {
    int tid = threadIdx.x;
    if (tid == 0) {
        float w12 = w[12];
        float d1 = 1.0f - w12 * w12;
        float d2 = 1.0f - w12 * w12 * w12;
        float a00, a01, a34, a314, a37, a310, a67, a617, a610,
              a920, a910, a164, a1614, a197, a1917, a2210, a2220;
        {
            float v0 = 1.0f - w[0], v1 = w[0];
            float m = fmaxf(v0, v1);
            float e0 = expf(v0 - m), e1 = expf(v1 - m);
            float s = e0 + e1;
            a00 = e0 / s; a01 = e1 / s;
        }
        {
            float v0 = w[1], v1 = w[3], v2 = d1, v3 = d2;
            float m = fmaxf(fmaxf(v0, v1), fmaxf(v2, v3));
            float e0 = expf(v0 - m), e1 = expf(v1 - m), e2 = expf(v2 - m), e3 = expf(v3 - m);
            float s = e0 + e1 + e2 + e3;
            a34 = e0 / s; a314 = e1 / s; a37 = e2 / s; a310 = e3 / s;
        }
        {
            float v0 = w[2], v1 = w[4], v2 = d1;
            float m = fmaxf(fmaxf(v0, v1), v2);
            float e0 = expf(v0 - m), e1 = expf(v1 - m), e2 = expf(v2 - m);
            float s = e0 + e1 + e2;
            a67 = e0 / s; a617 = e1 / s; a610 = e2 / s;
        }
        {
            float v0 = w[5], v1 = 1.0f - w[5];
            float m = fmaxf(v0, v1);
            float e0 = expf(v0 - m), e1 = expf(v1 - m);
            float s = e0 + e1;
            a920 = e0 / s; a910 = e1 / s;
        }
        {
            float v0 = w[6], v1 = 1.0f - w[9];
            float m = fmaxf(v0, v1);
            float e0 = expf(v0 - m), e1 = expf(v1 - m);
            float s = e0 + e1;
            a164 = e0 / s; a1614 = e1 / s;
        }
        {
            float v0 = w[7], v1 = 1.0f - w[10];
            float m = fmaxf(v0, v1);
            float e0 = expf(v0 - m), e1 = expf(v1 - m);
            float s = e0 + e1;
            a197 = e0 / s; a1917 = e1 / s;
        }
        {
            float v0 = w[8], v1 = 1.0f - w[11];
            float m = fmaxf(v0, v1);
            float e0 = expf(v0 - m), e1 = expf(v1 - m);
            float s = e0 + e1;
            a2210 = e0 / s; a2220 = e1 / s;
        }
        const float S6 = 1.0f / 6.0f, S36 = 1.0f / 36.0f, S216 = 1.0f / 216.0f;

        for (int l = 0; l < 32; l++) {
            g_src[l]  = make_int2(l, l);
            g_cp[l]   = make_float2(0.f, 0.f);
            g_cr[l]   = make_float2(0.f, 0.f);
            g_dsc[l]  = 1.0f;
            g_invd[l] = 1.0f;
        }
        g_src[0]  = make_int2(0, 0);   g_cp[0]  = make_float2(a00, 0);          g_cr[0]  = g_cp[0];
        g_src[1]  = make_int2(0, 1);   g_cp[1]  = make_float2(a01, 0);          g_cr[1]  = g_cp[1];
        g_src[2]  = make_int2(1, 2);   g_cp[2]  = make_float2(1, 0);            g_cr[2]  = g_cp[2];
        g_src[3]  = make_int2(2, 3);   g_cp[3]  = make_float2(1, 0);            g_cr[3]  = g_cp[3];
        g_src[4]  = make_int2(3, 16);  g_cp[4]  = make_float2(a34, a164);       g_cr[4]  = g_cp[4];
        g_src[5]  = make_int2(4, 5);   g_cp[5]  = make_float2(1, 0);            g_cr[5]  = g_cp[5];
        g_src[6]  = make_int2(5, 6);   g_cp[6]  = make_float2(1, 0);            g_cr[6]  = g_cp[6];
        g_src[7]  = make_int2(3, 6);   g_cp[7]  = make_float2(a37, a67);        g_cr[7]  = g_cp[7];
        g_src[8]  = make_int2(7, 25);  g_cp[8]  = make_float2(1, 1);            g_cr[8]  = g_cp[8];
        g_src[9]  = make_int2(8, 9);   g_cp[9]  = make_float2(1, 0);            g_cr[9]  = g_cp[9];
        g_src[10] = make_int2(3, 6);   g_cp[10] = make_float2(a310, a610);      g_cr[10] = g_cp[10];
        g_src[11] = make_int2(10, 24); g_cp[11] = make_float2(1, 1);            g_cr[11] = g_cp[11];
        g_src[12] = make_int2(11, 12); g_cp[12] = make_float2(1, 0);            g_cr[12] = g_cp[12];
        g_src[13] = make_int2(12, 13); g_cp[13] = make_float2(1, 0.5f);         g_cr[13] = g_cp[13];
        g_src[14] = make_int2(3, 16);  g_cp[14] = make_float2(a314, a1614);     g_cr[14] = g_cp[14];
        g_src[15] = make_int2(14, 15); g_cp[15] = make_float2(1, 0);            g_cr[15] = g_cp[15];
        g_src[16] = make_int2(15, 16); g_cp[16] = make_float2(1, 0);            g_cr[16] = g_cp[16];
        g_src[17] = make_int2(6, 19);  g_cp[17] = make_float2(a617 * S6, a1917 * S216);
                                       g_cr[17] = make_float2(a617, a1917);
        g_src[18] = make_int2(17, 18); g_cp[18] = make_float2(1, 0);            g_cr[18] = g_cp[18];
        g_src[19] = make_int2(18, 19); g_cp[19] = make_float2(1, 0);            g_cr[19] = g_cp[19];
        g_src[20] = make_int2(9, 22);  g_cp[20] = make_float2(a920 * S6, a2220 * S216);
                                       g_cr[20] = make_float2(a920, a2220);
        g_src[21] = make_int2(20, 21); g_cp[21] = make_float2(1, 0);            g_cr[21] = g_cp[21];
        g_src[22] = make_int2(21, 22); g_cp[22] = make_float2(1, 0);            g_cr[22] = g_cp[22];
        g_src[23] = make_int2(13, 23); g_cp[23] = make_float2(0.5f * S6, S6);
                                       g_cr[23] = make_float2(0.5f, 1.0f);
        g_src[24] = make_int2(9, 22);  g_cp[24] = make_float2(a910, a2210 * S36);
                                       g_cr[24] = make_float2(a910, a2210);
        g_src[25] = make_int2(19, 25); g_cp[25] = make_float2(a197 * S36, 0);
                                       g_cr[25] = make_float2(a197, 0);
        g_dsc[18] = 6.0f;  g_invd[18] = S6;
        g_dsc[19] = 36.0f; g_invd[19] = S36;
        g_dsc[21] = 6.0f;  g_invd[21] = S6;
        g_dsc[22] = 36.0f; g_invd[22] = S36;
        {
            float m = -1e30f;
            for (int i = 0; i < 24; i++) m = fmaxf(m, ik[i]);
            float e[24]; float s = 0.0f;
            for (int i = 0; i < 24; i++) { e[i] = expf(ik[i] - m); s += e[i]; }
            for (int i = 0; i < 24; i++) g_pi[i] = e[i] / s;
        }
    }
    __syncthreads();

    // Folded table: g = E_dest(ctx, lane) * cp(lane), per [ctx][lane].
    for (int idx = tid; idx < 64 * 32; idx += blockDim.x) {
        int ctx = idx >> 5;
        int l   = idx & 31;
        int st  = (l < 17) ? l : (l == 24) ? 10 : (l == 25) ? 7 : -1;
        float Ef;
        if (st >= 0) {
            int pq = ctx >> 2;
            int c  = ctx & 3;
            const float* p = ew + st * 64 + pq * 4;
            float v0 = p[0], v1 = p[1], v2 = p[2], v3 = p[3];
            float m = fmaxf(fmaxf(v0, v1), fmaxf(v2, v3));
            float e0 = expf(v0 - m), e1 = expf(v1 - m),
                  e2 = expf(v2 - m), e3 = expf(v3 - m);
            float ss = e0 + e1 + e2 + e3;
            float ec = (c == 0) ? e0 : (c == 1) ? e1 : (c == 2) ? e2 : e3;
            Ef = ec / ss;
        } else if (l < 24) {
            Ef = 1.0f;
        } else {
            Ef = 0.0f;
        }
        float2 cp = g_cp[l];
        g_Gtab[idx] = make_float2(Ef * cp.x, Ef * cp.y);
    }
}

// ---------------------------------------------------------------------------
// Forward kernel
// ---------------------------------------------------------------------------
__global__ __launch_bounds__(BLOCK)
void forward_kernel(const int* __restrict__ seq, float* __restrict__ out) {
    __shared__ __align__(16) float2 Tb[64 * 32];   // 16 KB
    {
        const float4* src = reinterpret_cast<const float4*>(g_Gtab);
        float4* dst = reinterpret_cast<float4*>(Tb);
        for (int i = threadIdx.x; i < 64 * 32 / 2; i += BLOCK) dst[i] = src[i];
    }
    __syncthreads();

    const unsigned FULL = 0xffffffffu;
    const int lane = threadIdx.x & 31;
    const int wid  = blockIdx.x * WPB + (threadIdx.x >> 5);

    const int2  si   = g_src[lane];
    const float invd = g_invd[lane];
    const float2* TbL = Tb + lane;

    const int4* q4 = reinterpret_cast<const int4*>(seq + wid * T_LEN);

    float beta = (lane < 24) ? g_pi[lane] : 0.0f;

    // t=1: raw-coef transition step, then beta scale.
    {
        const float2 cr  = g_cr[lane];
        const float  dsc = g_dsc[lane];
        float x0 = __shfl_sync(FULL, beta, si.x);
        float x1 = __shfl_sync(FULL, beta, si.y);
        beta = dsc * fmaf(cr.y, x1, cr.x * x0);
    }

    float ll = -3.58351893845611f;   // 2 * ln(1/6)

#define STEP(GV) do { \
        float x0 = __shfl_sync(FULL, beta, si.x); \
        float x1 = __shfl_sync(FULL, beta, si.y); \
        beta = fmaf((GV).y, x1, (GV).x * x0); \
    } while (0)

    // t=2, t=3
    int4 v = q4[0];
    int ctx;
    {
        int c2 = ((v.x << 4) | (v.y << 2) | v.z) & 63;
        int c3 = ((c2 << 2) | v.w) & 63;
        float2 e2 = TbL[c2 << 5];
        float2 e3 = TbL[c3 << 5];
        STEP(e2);
        STEP(e3);
        ctx = c3;
    }

    // Preload table pairs for block 1; seq prefetch distance 2.
    int4 u1 = q4[2];
    float2 e0, e1, e2, e3;
    {
        int4 u0 = q4[1];
        int c0 = ((ctx << 2) | u0.x) & 63;
        int c1 = ((c0  << 2) | u0.y) & 63;
        int c2c = ((c1 << 2) | u0.z) & 63;
        int c3c = ((c2c << 2) | u0.w) & 63;
        ctx = c3c;
        e0 = TbL[c0 << 5];
        e1 = TbL[c1 << 5];
        e2 = TbL[c2c << 5];
        e3 = TbL[c3c << 5];
    }

    float pending_inv = 1.0f;        // delayed renormalization factor

    for (int j = 1; j < 500; ++j) {
        int jn = (j < 498) ? j + 2 : 499;
        int4 up = q4[jn];

        // Next block's contexts + table loads (off-chain).
        int n0 = ((ctx << 2) | u1.x) & 63;
        int n1 = ((n0  << 2) | u1.y) & 63;
        int n2 = ((n1  << 2) | u1.z) & 63;
        int n3 = ((n2  << 2) | u1.w) & 63;
        ctx = n3;
        float2 f0 = TbL[n0 << 5];
        float2 f1 = TbL[n1 << 5];
        float2 f2 = TbL[n2 << 5];
        float2 f3 = TbL[n3 << 5];

        STEP(e0);
        STEP(e1);
        STEP(e2);
        STEP(e3);

        if ((j & 7) == 7) {          // every 32 steps
            beta *= pending_inv;     // on-chain: single mul
            float t = beta;          // butterfly/log/rcp off critical path
            t += __shfl_xor_sync(FULL, t, 16);
            t += __shfl_xor_sync(FULL, t, 8);
            t += __shfl_xor_sync(FULL, t, 4);
            t += __shfl_xor_sync(FULL, t, 2);
            t += __shfl_xor_sync(FULL, t, 1);
            ll += __logf(t);
            pending_inv = __fdividef(1.0f, t);
        }

        e0 = f0; e1 = f1; e2 = f2; e3 = f3;
        u1 = up;
    }
#undef STEP

    // Final: apply pending factor, beta -> alpha mass correction.
    {
        beta *= pending_inv;
        float t = beta * invd;
        t += __shfl_xor_sync(FULL, t, 16);
        t += __shfl_xor_sync(FULL, t, 8);
        t += __shfl_xor_sync(FULL, t, 4);
        t += __shfl_xor_sync(FULL, t, 2);
        t += __shfl_xor_sync(FULL, t, 1);
        ll += __logf(t);
    }

    if (lane == 0) out[wid] = ll;
}

// ---------------------------------------------------------------------------
// Launch
// ---------------------------------------------------------------------------
extern "C" void kernel_launch(void* const* d_in, const int* in_sizes, int n_in,
                              void* d_out, int out_size) {
    const float* transition_kernel = (const float*)d_in[0];
    const float* emission_kernel   = (const float*)d_in[1];
    const float* init_kernel       = (const float*)d_in[2];
    const int*   seq               = (const int*)d_in[3];
    float* out = (float*)d_out;

    setup_kernel<<<1, 256>>>(transition_kernel, emission_kernel, init_kernel);
    forward_kernel<<<BATCH / WPB, BLOCK>>>(seq, out);
}

// round 12
// speedup vs baseline: 1.2147x; 1.1675x over previous
#include <cuda_runtime.h>

// HMM forward CgpHmmCell (nCodons=2): 24 states + 2 helper lanes, batch=2048, T=2000.
// One warp per sequence, one lane per state; <=2 sources/lane.
// R12: context offsets PRECOMPUTED into a u16 stream (ctx*128 smem byte offset)
// by a separate kernel, removing all ctx ALU + buffering from the hot loop.
// Step = 2 shfl + LDS.32 + mul/fma/mul. Delayed renorm every 16 steps.

#define T_LEN 2000
#define BATCH 2048
#define WPB   2
#define BLOCK (WPB * 32)

__device__ int2   g_src[32];
__device__ float2 g_cp[32];
__device__ float2 g_cr[32];
__device__ float  g_dsc[32];
__device__ float  g_invd[32];
__device__ float  g_pi[24];
__device__ float  g_Etab[64 * 32];
__device__ unsigned short g_off[BATCH * T_LEN];   // 8 MB: per-step smem byte offsets

// ---------------------------------------------------------------------------
// Setup (tables identical to R9)
// ---------------------------------------------------------------------------
__global__ void setup_kernel(const float* __restrict__ w,
                             const float* __restrict__ ew,
                             const float* __restrict__ ik) {
    int tid = threadIdx.x;
    if (tid == 0) {
        float w12 = w[12];
        float d1 = 1.0f - w12 * w12;
        float d2 = 1.0f - w12 * w12 * w12;
        float a00, a01, a34, a314, a37, a310, a67, a617, a610,
              a920, a910, a164, a1614, a197, a1917, a2210, a2220;
        {
            float v0 = 1.0f - w[0], v1 = w[0];
            float m = fmaxf(v0, v1);
            float e0 = expf(v0 - m), e1 = expf(v1 - m);
            float s = e0 + e1;
            a00 = e0 / s; a01 = e1 / s;
        }
        {
            float v0 = w[1], v1 = w[3], v2 = d1, v3 = d2;
            float m = fmaxf(fmaxf(v0, v1), fmaxf(v2, v3));
            float e0 = expf(v0 - m), e1 = expf(v1 - m), e2 = expf(v2 - m), e3 = expf(v3 - m);
            float s = e0 + e1 + e2 + e3;
            a34 = e0 / s; a314 = e1 / s; a37 = e2 / s; a310 = e3 / s;
        }
        {
            float v0 = w[2], v1 = w[4], v2 = d1;
            float m = fmaxf(fmaxf(v0, v1), v2);
            float e0 = expf(v0 - m), e1 = expf(v1 - m), e2 = expf(v2 - m);
            float s = e0 + e1 + e2;
            a67 = e0 / s; a617 = e1 / s; a610 = e2 / s;
        }
        {
            float v0 = w[5], v1 = 1.0f - w[5];
            float m = fmaxf(v0, v1);
            float e0 = expf(v0 - m), e1 = expf(v1 - m);
            float s = e0 + e1;
            a920 = e0 / s; a910 = e1 / s;
        }
        {
            float v0 = w[6], v1 = 1.0f - w[9];
            float m = fmaxf(v0, v1);
            float e0 = expf(v0 - m), e1 = expf(v1 - m);
            float s = e0 + e1;
            a164 = e0 / s; a1614 = e1 / s;
        }
        {
            float v0 = w[7], v1 = 1.0f - w[10];
            float m = fmaxf(v0, v1);
            float e0 = expf(v0 - m), e1 = expf(v1 - m);
            float s = e0 + e1;
            a197 = e0 / s; a1917 = e1 / s;
        }
        {
            float v0 = w[8], v1 = 1.0f - w[11];
            float m = fmaxf(v0, v1);
            float e0 = expf(v0 - m), e1 = expf(v1 - m);
            float s = e0 + e1;
            a2210 = e0 / s; a2220 = e1 / s;
        }
        const float S6 = 1.0f / 6.0f, S36 = 1.0f / 36.0f, S216 = 1.0f / 216.0f;

        for (int l = 0; l < 32; l++) {
            g_src[l]  = make_int2(l, l);
            g_cp[l]   = make_float2(0.f, 0.f);
            g_cr[l]   = make_float2(0.f, 0.f);
            g_dsc[l]  = 1.0f;
            g_invd[l] = 1.0f;
        }
        g_src[0]  = make_int2(0, 0);   g_cp[0]  = make_float2(a00, 0);          g_cr[0]  = g_cp[0];
        g_src[1]  = make_int2(0, 1);   g_cp[1]  = make_float2(a01, 0);          g_cr[1]  = g_cp[1];
        g_src[2]  = make_int2(1, 2);   g_cp[2]  = make_float2(1, 0);            g_cr[2]  = g_cp[2];
        g_src[3]  = make_int2(2, 3);   g_cp[3]  = make_float2(1, 0);            g_cr[3]  = g_cp[3];
        g_src[4]  = make_int2(3, 16);  g_cp[4]  = make_float2(a34, a164);       g_cr[4]  = g_cp[4];
        g_src[5]  = make_int2(4, 5);   g_cp[5]  = make_float2(1, 0);            g_cr[5]  = g_cp[5];
        g_src[6]  = make_int2(5, 6);   g_cp[6]  = make_float2(1, 0);            g_cr[6]  = g_cp[6];
        g_src[7]  = make_int2(3, 6);   g_cp[7]  = make_float2(a37, a67);        g_cr[7]  = g_cp[7];
        g_src[8]  = make_int2(7, 25);  g_cp[8]  = make_float2(1, 1);            g_cr[8]  = g_cp[8];
        g_src[9]  = make_int2(8, 9);   g_cp[9]  = make_float2(1, 0);            g_cr[9]  = g_cp[9];
        g_src[10] = make_int2(3, 6);   g_cp[10] = make_float2(a310, a610);      g_cr[10] = g_cp[10];
        g_src[11] = make_int2(10, 24); g_cp[11] = make_float2(1, 1);            g_cr[11] = g_cp[11];
        g_src[12] = make_int2(11, 12); g_cp[12] = make_float2(1, 0);            g_cr[12] = g_cp[12];
        g_src[13] = make_int2(12, 13); g_cp[13] = make_float2(1, 0.5f);         g_cr[13] = g_cp[13];
        g_src[14] = make_int2(3, 16);  g_cp[14] = make_float2(a314, a1614);     g_cr[14] = g_cp[14];
        g_src[15] = make_int2(14, 15); g_cp[15] = make_float2(1, 0);            g_cr[15] = g_cp[15];
        g_src[16] = make_int2(15, 16); g_cp[16] = make_float2(1, 0);            g_cr[16] = g_cp[16];
        g_src[17] = make_int2(6, 19);  g_cp[17] = make_float2(a617 * S6, a1917 * S216);
                                       g_cr[17] = make_float2(a617, a1917);
        g_src[18] = make_int2(17, 18); g_cp[18] = make_float2(1, 0);            g_cr[18] = g_cp[18];
        g_src[19] = make_int2(18, 19); g_cp[19] = make_float2(1, 0);            g_cr[19] = g_cp[19];
        g_src[20] = make_int2(9, 22);  g_cp[20] = make_float2(a920 * S6, a2220 * S216);
                                       g_cr[20] = make_float2(a920, a2220);
        g_src[21] = make_int2(20, 21); g_cp[21] = make_float2(1, 0);            g_cr[21] = g_cp[21];
        g_src[22] = make_int2(21, 22); g_cp[22] = make_float2(1, 0);            g_cr[22] = g_cp[22];
        g_src[23] = make_int2(13, 23); g_cp[23] = make_float2(0.5f * S6, S6);
                                       g_cr[23] = make_float2(0.5f, 1.0f);
        g_src[24] = make_int2(9, 22);  g_cp[24] = make_float2(a910, a2210 * S36);
                                       g_cr[24] = make_float2(a910, a2210);
        g_src[25] = make_int2(19, 25); g_cp[25] = make_float2(a197 * S36, 0);
                                       g_cr[25] = make_float2(a197, 0);
        g_dsc[18] = 6.0f;  g_invd[18] = S6;
        g_dsc[19] = 36.0f; g_invd[19] = S36;
        g_dsc[21] = 6.0f;  g_invd[21] = S6;
        g_dsc[22] = 36.0f; g_invd[22] = S36;
        {
            float m = -1e30f;
            for (int i = 0; i < 24; i++) m = fmaxf(m, ik[i]);
            float e[24]; float s = 0.0f;
            for (int i = 0; i < 24; i++) { e[i] = expf(ik[i] - m); s += e[i]; }
            for (int i = 0; i < 24; i++) g_pi[i] = e[i] / s;
        }
    }
    __syncthreads();

    for (int idx = tid; idx < 64 * 32; idx += blockDim.x) {
        int ctx = idx >> 5;
        int l   = idx & 31;
        int st  = (l < 17) ? l : (l == 24) ? 10 : (l == 25) ? 7 : -1;
        float val;
        if (st >= 0) {
            int pq = ctx >> 2;
            int c  = ctx & 3;
            const float* p = ew + st * 64 + pq * 4;
            float v0 = p[0], v1 = p[1], v2 = p[2], v3 = p[3];
            float m = fmaxf(fmaxf(v0, v1), fmaxf(v2, v3));
            float e0 = expf(v0 - m), e1 = expf(v1 - m),
                  e2 = expf(v2 - m), e3 = expf(v3 - m);
            float ss = e0 + e1 + e2 + e3;
            float ec = (c == 0) ? e0 : (c == 1) ? e1 : (c == 2) ? e2 : e3;
            val = ec / ss;
        } else if (l < 24) {
            val = 1.0f;
        } else {
            val = 0.0f;
        }
        g_Etab[idx] = val;
    }
}

// ---------------------------------------------------------------------------
// Context preprocessing: g_off[b*2000 + p] = ctx(step p)*128 for p in [0,1998)
// where step p corresponds to t=p+2, ctx = (s[p]<<4)|(s[p+1]<<2)|s[p+2].
// Each thread produces 8 offsets from 3 aligned int4 loads.
// ---------------------------------------------------------------------------
__global__ void ctx_kernel(const int* __restrict__ seq) {
    int tidg = blockIdx.x * blockDim.x + threadIdx.x;   // 0 .. 2048*250-1
    int b = tidg / 250;
    int c = tidg % 250;
    const int4* row = reinterpret_cast<const int4*>(seq + b * T_LEN);
    int i = c * 2;                       // int4 index; outputs start p0 = c*8
    int4 a = row[i];
    int4 d = row[i + 1];
    int4 e = (i + 2 < 500) ? row[i + 2] : make_int4(0, 0, 0, 0);
    int s[12] = {a.x, a.y, a.z, a.w, d.x, d.y, d.z, d.w, e.x, e.y, e.z, e.w};
    unsigned short o[8];
    int p0 = c * 8;
    #pragma unroll
    for (int k = 0; k < 8; k++) {
        int ctx = (s[k] << 4) | (s[k + 1] << 2) | s[k + 2];
        o[k] = (p0 + k < 1998) ? (unsigned short)(ctx << 7) : (unsigned short)0;
    }
    reinterpret_cast<int4*>(g_off)[tidg] = *reinterpret_cast<int4*>(o);
}

// ---------------------------------------------------------------------------
// Forward kernel
// ---------------------------------------------------------------------------
__global__ __launch_bounds__(BLOCK)
void forward_kernel(float* __restrict__ out) {
    __shared__ __align__(16) float Tb[64 * 32];   // 8 KB
    {
        const float4* src = reinterpret_cast<const float4*>(g_Etab);
        float4* dst = reinterpret_cast<float4*>(Tb);
        for (int i = threadIdx.x; i < 64 * 32 / 4; i += BLOCK) dst[i] = src[i];
    }
    __syncthreads();

    const unsigned FULL = 0xffffffffu;
    const int lane = threadIdx.x & 31;
    const int wid  = blockIdx.x * WPB + (threadIdx.x >> 5);

    const int2   si   = g_src[lane];
    const float2 cp   = g_cp[lane];
    const float  invd = g_invd[lane];
    const char*  tbB  = reinterpret_cast<const char*>(Tb) + lane * 4;

    const uint4* offp = reinterpret_cast<const uint4*>(g_off + (size_t)wid * T_LEN);

    float beta = (lane < 24) ? g_pi[lane] : 0.0f;

    // t=1: raw-coef transition step, then beta scale.
    {
        const float2 cr  = g_cr[lane];
        const float  dsc = g_dsc[lane];
        float x0 = __shfl_sync(FULL, beta, si.x);
        float x1 = __shfl_sync(FULL, beta, si.y);
        beta = dsc * fmaf(cr.y, x1, cr.x * x0);
    }

    float ll = -3.58351893845611f;   // 2 * ln(1/6)
    float pending_inv = 1.0f;

#define STEP(OFF) do { \
        float x0 = __shfl_sync(FULL, beta, si.x); \
        float x1 = __shfl_sync(FULL, beta, si.y); \
        float ev = *reinterpret_cast<const float*>(tbB + (OFF)); \
        beta = ev * fmaf(cp.y, x1, cp.x * x0); \
    } while (0)

    // Main loop: 249 chunks of 8 steps (1992 steps), prefetch distance 2.
    uint4 c0 = offp[0];
    uint4 c1 = offp[1];
    #pragma unroll 2
    for (int j = 0; j < 249; ++j) {
        uint4 cn = offp[(j + 2 < 250) ? j + 2 : 249];
        unsigned o0 = c0.x & 0xffffu, o1 = c0.x >> 16;
        unsigned o2 = c0.y & 0xffffu, o3 = c0.y >> 16;
        unsigned o4 = c0.z & 0xffffu, o5 = c0.z >> 16;
        unsigned o6 = c0.w & 0xffffu, o7 = c0.w >> 16;
        STEP(o0); STEP(o1); STEP(o2); STEP(o3);
        STEP(o4); STEP(o5); STEP(o6); STEP(o7);
        if ((j & 1) == 1) {          // every 16 steps, delayed apply
            beta *= pending_inv;
            float t = beta;
            t += __shfl_xor_sync(FULL, t, 16);
            t += __shfl_xor_sync(FULL, t, 8);
            t += __shfl_xor_sync(FULL, t, 4);
            t += __shfl_xor_sync(FULL, t, 2);
            t += __shfl_xor_sync(FULL, t, 1);
            ll += __logf(t);
            pending_inv = __fdividef(1.0f, t);
        }
        c0 = c1; c1 = cn;
    }

    // Epilogue: 6 remaining steps (chunk 249, offsets 0..5)
    {
        unsigned o0 = c0.x & 0xffffu, o1 = c0.x >> 16;
        unsigned o2 = c0.y & 0xffffu, o3 = c0.y >> 16;
        unsigned o4 = c0.z & 0xffffu, o5 = c0.z >> 16;
        STEP(o0); STEP(o1); STEP(o2); STEP(o3); STEP(o4); STEP(o5);
    }
#undef STEP

    // Final: apply pending factor, beta -> alpha mass correction.
    {
        beta *= pending_inv;
        float t = beta * invd;
        t += __shfl_xor_sync(FULL, t, 16);
        t += __shfl_xor_sync(FULL, t, 8);
        t += __shfl_xor_sync(FULL, t, 4);
        t += __shfl_xor_sync(FULL, t, 2);
        t += __shfl_xor_sync(FULL, t, 1);
        ll += __logf(t);
    }

    if (lane == 0) out[wid] = ll;
}

// ---------------------------------------------------------------------------
// Launch
// ---------------------------------------------------------------------------
extern "C" void kernel_launch(void* const* d_in, const int* in_sizes, int n_in,
                              void* d_out, int out_size) {
    const float* transition_kernel = (const float*)d_in[0];
    const float* emission_kernel   = (const float*)d_in[1];
    const float* init_kernel       = (const float*)d_in[2];
    const int*   seq               = (const int*)d_in[3];
    float* out = (float*)d_out;

    setup_kernel<<<1, 256>>>(transition_kernel, emission_kernel, init_kernel);
    ctx_kernel<<<(BATCH * 250 + 255) / 256, 256>>>(seq);
    forward_kernel<<<BATCH / WPB, BLOCK>>>(out);
}

// round 13
// speedup vs baseline: 1.2633x; 1.0400x over previous
#include <cuda_runtime.h>

// HMM forward CgpHmmCell (nCodons=2): 24 states + 2 helper lanes, batch=2048, T=2000.
// One warp per sequence, one lane per state; <=2 sources/lane.
// R13: setup merged into ctx kernel (block 2000) and parallelized with fast math;
// forward kernel identical to R12 (2 shfl + LDS.32 per step, precomputed offsets).

#define T_LEN 2000
#define BATCH 2048
#define WPB   2
#define BLOCK (WPB * 32)

__device__ int2   g_src[32];
__device__ float2 g_cp[32];
__device__ float2 g_cr[32];
__device__ float  g_dsc[32];
__device__ float  g_invd[32];
__device__ float  g_pi[24];
__device__ float  g_Etab[64 * 32];
__device__ unsigned short g_off[BATCH * T_LEN];   // per-step smem byte offsets

// ---------------------------------------------------------------------------
// Combined prep kernel:
//   blocks 0..1999  : context-offset stream (8 offsets per thread)
//   block  2000     : coefficient + emission-table setup (parallelized)
// ---------------------------------------------------------------------------
__global__ void prep_kernel(const int* __restrict__ seq,
                            const float* __restrict__ w,
                            const float* __restrict__ ew,
                            const float* __restrict__ ik) {
    if (blockIdx.x < 2000) {
        int tidg = blockIdx.x * blockDim.x + threadIdx.x;   // 0 .. 2048*250-1
        int b = tidg / 250;
        int c = tidg % 250;
        const int4* row = reinterpret_cast<const int4*>(seq + b * T_LEN);
        int i = c * 2;
        int4 a = row[i];
        int4 d = row[i + 1];
        int4 e = (i + 2 < 500) ? row[i + 2] : make_int4(0, 0, 0, 0);
        int s[12] = {a.x, a.y, a.z, a.w, d.x, d.y, d.z, d.w, e.x, e.y, e.z, e.w};
        unsigned short o[8];
        int p0 = c * 8;
        #pragma unroll
        for (int k = 0; k < 8; k++) {
            int ctx = (s[k] << 4) | (s[k + 1] << 2) | s[k + 2];
            o[k] = (p0 + k < 1998) ? (unsigned short)(ctx << 7) : (unsigned short)0;
        }
        reinterpret_cast<int4*>(g_off)[tidg] = *reinterpret_cast<int4*>(o);
        return;
    }

    // ---------------- setup block ----------------
    __shared__ float sv[17];
    int tid = threadIdx.x;

    // Parallel softmax groups (threads 0..6) + pi (thread 7).
    if (tid < 8) {
        float w12 = w[12];
        float d1 = 1.0f - w12 * w12;
        float d2 = 1.0f - w12 * w12 * w12;
        switch (tid) {
        case 0: {   // row 0: (1-w0, w0)
            float e0 = __expf(1.0f - w[0]), e1 = __expf(w[0]);
            float inv = __fdividef(1.0f, e0 + e1);
            sv[0] = e0 * inv; sv[1] = e1 * inv;
        } break;
        case 1: {   // row 3: (w1, w3, d1, d2)
            float e0 = __expf(w[1]), e1 = __expf(w[3]),
                  e2 = __expf(d1),  e3 = __expf(d2);
            float inv = __fdividef(1.0f, e0 + e1 + e2 + e3);
            sv[2] = e0 * inv; sv[3] = e1 * inv; sv[4] = e2 * inv; sv[5] = e3 * inv;
        } break;
        case 2: {   // row 6: (w2, w4, d1)
            float e0 = __expf(w[2]), e1 = __expf(w[4]), e2 = __expf(d1);
            float inv = __fdividef(1.0f, e0 + e1 + e2);
            sv[6] = e0 * inv; sv[7] = e1 * inv; sv[8] = e2 * inv;
        } break;
        case 3: {   // row 9: (w5, 1-w5)
            float e0 = __expf(w[5]), e1 = __expf(1.0f - w[5]);
            float inv = __fdividef(1.0f, e0 + e1);
            sv[9] = e0 * inv; sv[10] = e1 * inv;
        } break;
        case 4: {   // row 16: (w6, 1-w9)
            float e0 = __expf(w[6]), e1 = __expf(1.0f - w[9]);
            float inv = __fdividef(1.0f, e0 + e1);
            sv[11] = e0 * inv; sv[12] = e1 * inv;
        } break;
        case 5: {   // row 19: (w7, 1-w10)
            float e0 = __expf(w[7]), e1 = __expf(1.0f - w[10]);
            float inv = __fdividef(1.0f, e0 + e1);
            sv[13] = e0 * inv; sv[14] = e1 * inv;
        } break;
        case 6: {   // row 22: (w8, 1-w11)
            float e0 = __expf(w[8]), e1 = __expf(1.0f - w[11]);
            float inv = __fdividef(1.0f, e0 + e1);
            sv[15] = e0 * inv; sv[16] = e1 * inv;
        } break;
        case 7: {   // pi = softmax(ik)
            float e[24]; float s = 0.0f;
            #pragma unroll
            for (int i = 0; i < 24; i++) { e[i] = __expf(ik[i]); s += e[i]; }
            float inv = __fdividef(1.0f, s);
            #pragma unroll
            for (int i = 0; i < 24; i++) g_pi[i] = e[i] * inv;
        } break;
        }
    }
    __syncthreads();

    if (tid == 0) {
        float a00 = sv[0],  a01   = sv[1];
        float a34 = sv[2],  a314  = sv[3],  a37 = sv[4], a310 = sv[5];
        float a67 = sv[6],  a617  = sv[7],  a610 = sv[8];
        float a920 = sv[9], a910  = sv[10];
        float a164 = sv[11], a1614 = sv[12];
        float a197 = sv[13], a1917 = sv[14];
        float a2210 = sv[15], a2220 = sv[16];
        const float S6 = 1.0f / 6.0f, S36 = 1.0f / 36.0f, S216 = 1.0f / 216.0f;

        for (int l = 0; l < 32; l++) {
            g_src[l]  = make_int2(l, l);
            g_cp[l]   = make_float2(0.f, 0.f);
            g_cr[l]   = make_float2(0.f, 0.f);
            g_dsc[l]  = 1.0f;
            g_invd[l] = 1.0f;
        }
        g_src[0]  = make_int2(0, 0);   g_cp[0]  = make_float2(a00, 0);          g_cr[0]  = g_cp[0];
        g_src[1]  = make_int2(0, 1);   g_cp[1]  = make_float2(a01, 0);          g_cr[1]  = g_cp[1];
        g_src[2]  = make_int2(1, 2);   g_cp[2]  = make_float2(1, 0);            g_cr[2]  = g_cp[2];
        g_src[3]  = make_int2(2, 3);   g_cp[3]  = make_float2(1, 0);            g_cr[3]  = g_cp[3];
        g_src[4]  = make_int2(3, 16);  g_cp[4]  = make_float2(a34, a164);       g_cr[4]  = g_cp[4];
        g_src[5]  = make_int2(4, 5);   g_cp[5]  = make_float2(1, 0);            g_cr[5]  = g_cp[5];
        g_src[6]  = make_int2(5, 6);   g_cp[6]  = make_float2(1, 0);            g_cr[6]  = g_cp[6];
        g_src[7]  = make_int2(3, 6);   g_cp[7]  = make_float2(a37, a67);        g_cr[7]  = g_cp[7];
        g_src[8]  = make_int2(7, 25);  g_cp[8]  = make_float2(1, 1);            g_cr[8]  = g_cp[8];
        g_src[9]  = make_int2(8, 9);   g_cp[9]  = make_float2(1, 0);            g_cr[9]  = g_cp[9];
        g_src[10] = make_int2(3, 6);   g_cp[10] = make_float2(a310, a610);      g_cr[10] = g_cp[10];
        g_src[11] = make_int2(10, 24); g_cp[11] = make_float2(1, 1);            g_cr[11] = g_cp[11];
        g_src[12] = make_int2(11, 12); g_cp[12] = make_float2(1, 0);            g_cr[12] = g_cp[12];
        g_src[13] = make_int2(12, 13); g_cp[13] = make_float2(1, 0.5f);         g_cr[13] = g_cp[13];
        g_src[14] = make_int2(3, 16);  g_cp[14] = make_float2(a314, a1614);     g_cr[14] = g_cp[14];
        g_src[15] = make_int2(14, 15); g_cp[15] = make_float2(1, 0);            g_cr[15] = g_cp[15];
        g_src[16] = make_int2(15, 16); g_cp[16] = make_float2(1, 0);            g_cr[16] = g_cp[16];
        g_src[17] = make_int2(6, 19);  g_cp[17] = make_float2(a617 * S6, a1917 * S216);
                                       g_cr[17] = make_float2(a617, a1917);
        g_src[18] = make_int2(17, 18); g_cp[18] = make_float2(1, 0);            g_cr[18] = g_cp[18];
        g_src[19] = make_int2(18, 19); g_cp[19] = make_float2(1, 0);            g_cr[19] = g_cp[19];
        g_src[20] = make_int2(9, 22);  g_cp[20] = make_float2(a920 * S6, a2220 * S216);
                                       g_cr[20] = make_float2(a920, a2220);
        g_src[21] = make_int2(20, 21); g_cp[21] = make_float2(1, 0);            g_cr[21] = g_cp[21];
        g_src[22] = make_int2(21, 22); g_cp[22] = make_float2(1, 0);            g_cr[22] = g_cp[22];
        g_src[23] = make_int2(13, 23); g_cp[23] = make_float2(0.5f * S6, S6);
                                       g_cr[23] = make_float2(0.5f, 1.0f);
        g_src[24] = make_int2(9, 22);  g_cp[24] = make_float2(a910, a2210 * S36);
                                       g_cr[24] = make_float2(a910, a2210);
        g_src[25] = make_int2(19, 25); g_cp[25] = make_float2(a197 * S36, 0);
                                       g_cr[25] = make_float2(a197, 0);
        g_dsc[18] = 6.0f;  g_invd[18] = S6;
        g_dsc[19] = 36.0f; g_invd[19] = S36;
        g_dsc[21] = 6.0f;  g_invd[21] = S6;
        g_dsc[22] = 36.0f; g_invd[22] = S36;
    }

    // E table: parallel over all 256 threads, fast math (values are ~exp(±0.2)).
    for (int idx = tid; idx < 64 * 32; idx += blockDim.x) {
        int ctx = idx >> 5;
        int l   = idx & 31;
        int st  = (l < 17) ? l : (l == 24) ? 10 : (l == 25) ? 7 : -1;
        float val;
        if (st >= 0) {
            int pq = ctx >> 2;
            int c  = ctx & 3;
            const float* p = ew + st * 64 + pq * 4;
            float e0 = __expf(p[0]), e1 = __expf(p[1]),
                  e2 = __expf(p[2]), e3 = __expf(p[3]);
            float inv = __fdividef(1.0f, e0 + e1 + e2 + e3);
            float ec = (c == 0) ? e0 : (c == 1) ? e1 : (c == 2) ? e2 : e3;
            val = ec * inv;
        } else if (l < 24) {
            val = 1.0f;
        } else {
            val = 0.0f;
        }
        g_Etab[idx] = val;
    }
}

// ---------------------------------------------------------------------------
// Forward kernel (identical to R12)
// ---------------------------------------------------------------------------
__global__ __launch_bounds__(BLOCK)
void forward_kernel(float* __restrict__ out) {
    __shared__ __align__(16) float Tb[64 * 32];   // 8 KB
    {
        const float4* src = reinterpret_cast<const float4*>(g_Etab);
        float4* dst = reinterpret_cast<float4*>(Tb);
        for (int i = threadIdx.x; i < 64 * 32 / 4; i += BLOCK) dst[i] = src[i];
    }
    __syncthreads();

    const unsigned FULL = 0xffffffffu;
    const int lane = threadIdx.x & 31;
    const int wid  = blockIdx.x * WPB + (threadIdx.x >> 5);

    const int2   si   = g_src[lane];
    const float2 cp   = g_cp[lane];
    const float  invd = g_invd[lane];
    const char*  tbB  = reinterpret_cast<const char*>(Tb) + lane * 4;

    const uint4* offp = reinterpret_cast<const uint4*>(g_off + (size_t)wid * T_LEN);

    float beta = (lane < 24) ? g_pi[lane] : 0.0f;

    // t=1: raw-coef transition step, then beta scale.
    {
        const float2 cr  = g_cr[lane];
        const float  dsc = g_dsc[lane];
        float x0 = __shfl_sync(FULL, beta, si.x);
        float x1 = __shfl_sync(FULL, beta, si.y);
        beta = dsc * fmaf(cr.y, x1, cr.x * x0);
    }

    float ll = -3.58351893845611f;   // 2 * ln(1/6)
    float pending_inv = 1.0f;

#define STEP(OFF) do { \
        float x0 = __shfl_sync(FULL, beta, si.x); \
        float x1 = __shfl_sync(FULL, beta, si.y); \
        float ev = *reinterpret_cast<const float*>(tbB + (OFF)); \
        beta = ev * fmaf(cp.y, x1, cp.x * x0); \
    } while (0)

    uint4 c0 = offp[0];
    uint4 c1 = offp[1];
    #pragma unroll 2
    for (int j = 0; j < 249; ++j) {
        uint4 cn = offp[(j + 2 < 250) ? j + 2 : 249];
        unsigned o0 = c0.x & 0xffffu, o1 = c0.x >> 16;
        unsigned o2 = c0.y & 0xffffu, o3 = c0.y >> 16;
        unsigned o4 = c0.z & 0xffffu, o5 = c0.z >> 16;
        unsigned o6 = c0.w & 0xffffu, o7 = c0.w >> 16;
        STEP(o0); STEP(o1); STEP(o2); STEP(o3);
        STEP(o4); STEP(o5); STEP(o6); STEP(o7);
        if ((j & 1) == 1) {          // every 16 steps, delayed apply
            beta *= pending_inv;
            float t = beta;
            t += __shfl_xor_sync(FULL, t, 16);
            t += __shfl_xor_sync(FULL, t, 8);
            t += __shfl_xor_sync(FULL, t, 4);
            t += __shfl_xor_sync(FULL, t, 2);
            t += __shfl_xor_sync(FULL, t, 1);
            ll += __logf(t);
            pending_inv = __fdividef(1.0f, t);
        }
        c0 = c1; c1 = cn;
    }

    // Epilogue: 6 remaining steps.
    {
        unsigned o0 = c0.x & 0xffffu, o1 = c0.x >> 16;
        unsigned o2 = c0.y & 0xffffu, o3 = c0.y >> 16;
        unsigned o4 = c0.z & 0xffffu, o5 = c0.z >> 16;
        STEP(o0); STEP(o1); STEP(o2); STEP(o3); STEP(o4); STEP(o5);
    }
#undef STEP

    // Final: apply pending factor, beta -> alpha mass correction.
    {
        beta *= pending_inv;
        float t = beta * invd;
        t += __shfl_xor_sync(FULL, t, 16);
        t += __shfl_xor_sync(FULL, t, 8);
        t += __shfl_xor_sync(FULL, t, 4);
        t += __shfl_xor_sync(FULL, t, 2);
        t += __shfl_xor_sync(FULL, t, 1);
        ll += __logf(t);
    }

    if (lane == 0) out[wid] = ll;
}

// ---------------------------------------------------------------------------
// Launch
// ---------------------------------------------------------------------------
extern "C" void kernel_launch(void* const* d_in, const int* in_sizes, int n_in,
                              void* d_out, int out_size) {
    const float* transition_kernel = (const float*)d_in[0];
    const float* emission_kernel   = (const float*)d_in[1];
    const float* init_kernel       = (const float*)d_in[2];
    const int*   seq               = (const int*)d_in[3];
    float* out = (float*)d_out;

    prep_kernel<<<2001, 256>>>(seq, transition_kernel, emission_kernel, init_kernel);
    forward_kernel<<<BATCH / WPB, BLOCK>>>(out);
}